// round 9
// baseline (speedup 1.0000x reference)
#include <cuda_runtime.h>
#include <cuda_fp16.h>
#include <math.h>
#include <stdint.h>

// Problem constants
#define Bv     4
#define Nv     8192
#define Sv     2048
#define LOWD   512
#define SKIPD  256
#define OUTD   256
#define IND    768

// Scratch (device globals; no allocation allowed)
__device__ float  g_w[(size_t)Bv * Nv * 3];
__device__ int    g_idx[(size_t)Bv * Nv * 3];
__device__ __half g_W1h[(size_t)OUTD * IND];     // W1^T fp16 [n][k]
__device__ __half g_W2h[(size_t)OUTD * OUTD];    // W2^T fp16 [n][k]
__device__ __half g_Gh[(size_t)Bv * Sv * OUTD];  // feat_lo @ W1[256:] (fp16, 4 MB)

// ---------------------------------------------------------------------------
// Helpers
// ---------------------------------------------------------------------------
__device__ __forceinline__ uint32_t smem_u32(const void* p) {
    uint32_t a;
    asm("{ .reg .u64 t; cvta.to.shared.u64 t, %1; cvt.u32.u64 %0, t; }"
        : "=r"(a) : "l"(p));
    return a;
}
__device__ __forceinline__ void ldmx4(uint32_t (&r)[4], uint32_t addr) {
    asm volatile("ldmatrix.sync.aligned.m8n8.x4.shared.b16 {%0,%1,%2,%3}, [%4];"
                 : "=r"(r[0]), "=r"(r[1]), "=r"(r[2]), "=r"(r[3]) : "r"(addr));
}
__device__ __forceinline__ void mma16816(float (&d)[4], const uint32_t (&a)[4],
                                         uint32_t b0, uint32_t b1) {
    asm volatile("mma.sync.aligned.m16n8k16.row.col.f32.f16.f16.f32 "
                 "{%0,%1,%2,%3}, {%4,%5,%6,%7}, {%8,%9}, {%0,%1,%2,%3};"
                 : "+f"(d[0]), "+f"(d[1]), "+f"(d[2]), "+f"(d[3])
                 : "r"(a[0]), "r"(a[1]), "r"(a[2]), "r"(a[3]), "r"(b0), "r"(b1));
}
__device__ __forceinline__ void cpasync16(uint32_t s, const void* g) {
    asm volatile("cp.async.cg.shared.global [%0], [%1], 16;" :: "r"(s), "l"(g));
}
__device__ __forceinline__ void cp_commit() {
    asm volatile("cp.async.commit_group;" ::: "memory");
}
__device__ __forceinline__ void cp_wait_all() {
    asm volatile("cp.async.wait_group 0;" ::: "memory");
}
__device__ __forceinline__ uint32_t packh2(float a, float b) {
    __half2 h = __floats2half2_rn(a, b);
    return *(uint32_t*)&h;
}

#define ASTRIDE  72      // halfs
#define HSTRIDE  264     // halfs

// ---------------------------------------------------------------------------
// Transposes: fp32 [K][N] -> fp16 [N][K] for W1 (K=768) and W2 (K=256)
// ---------------------------------------------------------------------------
__global__ void transpose_both(const float* __restrict__ W1, const float* __restrict__ W2,
                               __half* __restrict__ w1h, __half* __restrict__ w2h) {
    __shared__ float t[32][33];
    const int tx = threadIdx.x, ty = threadIdx.y;
    const float* src; __half* dst; int K, k0;
    if (blockIdx.y < 24) { src = W1; dst = w1h; K = IND;  k0 = blockIdx.y * 32; }
    else                 { src = W2; dst = w2h; K = OUTD; k0 = (blockIdx.y - 24) * 32; }
    const int n0 = blockIdx.x * 32;
#pragma unroll
    for (int i = 0; i < 32; i += 8)
        t[ty + i][tx] = src[(size_t)(k0 + ty + i) * OUTD + n0 + tx];
    __syncthreads();
#pragma unroll
    for (int i = 0; i < 32; i += 8)
        dst[(size_t)(n0 + ty + i) * K + k0 + tx] = __float2half_rn(t[tx][ty + i]);
}

// ---------------------------------------------------------------------------
// PREP kernel (R6 configuration — measured best):
//   [0, 128)   gemm_g : G = feat_lo @ W1[256:]^T -> g_Gh (fp16), B via cp.async of g_W1h
//   [128, 256) knn    : full-scan 3-NN + IDW (256 queries/block)
// ---------------------------------------------------------------------------
#define GA_BYTES 9216     // 64 * 72 * 2
#define GB_BYTES 36864    // 256 * 72 * 2
#define GSMEM    (2 * GA_BYTES + 2 * GB_BYTES)   // 92160

__device__ __forceinline__ void knn_body(char* sm,
                                         const float* __restrict__ xyz_hi,
                                         const float* __restrict__ xyz_lo) {
    float4* P = (float4*)sm;   // 32 KB
    const int bid   = blockIdx.x - 128;
    const int b     = bid >> 5;
    const int qbase = (bid & 31) * 256;
    const int tid   = threadIdx.x;

    for (int s = tid; s < Sv; s += 256) {
        float x = xyz_lo[((size_t)b * Sv + s) * 3 + 0];
        float y = xyz_lo[((size_t)b * Sv + s) * 3 + 1];
        float z = xyz_lo[((size_t)b * Sv + s) * 3 + 2];
        P[s] = make_float4(-2.0f * x, -2.0f * y, -2.0f * z,
                           fmaf(z, z, fmaf(y, y, x * x)));
    }
    __syncthreads();

    const int q = b * Nv + qbase + tid;
    const float qx = xyz_hi[(size_t)q * 3 + 0];
    const float qy = xyz_hi[(size_t)q * 3 + 1];
    const float qz = xyz_hi[(size_t)q * 3 + 2];
    const float qq = fmaf(qz, qz, fmaf(qy, qy, qx * qx));

    float d0 = 1e30f, d1 = 1e30f, d2 = 1e30f;
    int   i0 = 0,     i1 = 0,     i2 = 0;

#define INS3(E, S)                                                       \
    {                                                                    \
        bool l2 = (E) < d2, l1 = (E) < d1, l0 = (E) < d0;                \
        d2 = l1 ? d1 : (l2 ? (E) : d2);  i2 = l1 ? i1 : (l2 ? (S) : i2); \
        d1 = l0 ? d0 : (l1 ? (E) : d1);  i1 = l0 ? i0 : (l1 ? (S) : i1); \
        d0 = l0 ? (E) : d0;              i0 = l0 ? (S) : i0;             \
    }
    for (int s = 0; s < Sv; s += 4) {
        float4 p0 = P[s + 0], p1 = P[s + 1], p2 = P[s + 2], p3 = P[s + 3];
        float e0 = fmaf(qx, p0.x, fmaf(qy, p0.y, fmaf(qz, p0.z, p0.w)));
        float e1 = fmaf(qx, p1.x, fmaf(qy, p1.y, fmaf(qz, p1.z, p1.w)));
        float e2 = fmaf(qx, p2.x, fmaf(qy, p2.y, fmaf(qz, p2.z, p2.w)));
        float e3 = fmaf(qx, p3.x, fmaf(qy, p3.y, fmaf(qz, p3.z, p3.w)));
        float m = fminf(fminf(e0, e1), fminf(e2, e3));
        if (m < d2) {
            INS3(e0, s + 0); INS3(e1, s + 1); INS3(e2, s + 2); INS3(e3, s + 3);
        }
    }
#undef INS3

    float r0 = 1.0f / (sqrtf(fmaxf(d0 + qq, 0.0f)) + 1e-8f);
    float r1 = 1.0f / (sqrtf(fmaxf(d1 + qq, 0.0f)) + 1e-8f);
    float r2 = 1.0f / (sqrtf(fmaxf(d2 + qq, 0.0f)) + 1e-8f);
    float inv = 1.0f / (r0 + r1 + r2);
    g_w[(size_t)q * 3 + 0] = r0 * inv;
    g_w[(size_t)q * 3 + 1] = r1 * inv;
    g_w[(size_t)q * 3 + 2] = r2 * inv;
    g_idx[(size_t)q * 3 + 0] = i0;
    g_idx[(size_t)q * 3 + 1] = i1;
    g_idx[(size_t)q * 3 + 2] = i2;
}

__device__ __forceinline__ void gemm_g_body(char* sm, const float* __restrict__ feat_lo) {
    const uint32_t sb = smem_u32(sm);
    const int tid    = threadIdx.x;
    const int wid    = tid >> 5;
    const int lane   = tid & 31;
    const int warp_m = wid & 1;
    const int warp_n = wid >> 1;
    const int g0     = blockIdx.x * 64;

    const uint32_t uA[2] = { sb, sb + GA_BYTES };
    const uint32_t uB[2] = { sb + 2 * GA_BYTES, sb + 2 * GA_BYTES + GB_BYTES };

    const int a_row15 = lane & 15;
    const int a_k8    = (lane & 16) ? 8 : 0;
    const int b_noff  = (lane & 7) + ((lane & 16) ? 8 : 0);
    const int b_k8    = (lane & 8) ? 8 : 0;
    const int fx = tid & 15, r0 = tid >> 4;

    float acc[2][8][4];
#pragma unroll
    for (int mt = 0; mt < 2; mt++)
#pragma unroll
        for (int nt = 0; nt < 8; nt++)
#pragma unroll
            for (int e = 0; e < 4; e++) acc[mt][nt][e] = 0.0f;

#define GBUILD_A(K0, BUF)                                                         \
    do {                                                                          \
        char* Ab = sm + (BUF) * GA_BYTES;                                         \
        _Pragma("unroll")                                                         \
        for (int i = 0; i < 4; i++) {                                             \
            const int row = r0 + i * 16;                                          \
            float4 v = *(const float4*)(feat_lo + (size_t)(g0 + row) * LOWD + (K0) + fx * 4); \
            *(uint2*)(Ab + row * (ASTRIDE * 2) + fx * 8) =                        \
                make_uint2(packh2(v.x, v.y), packh2(v.z, v.w));                   \
        }                                                                         \
    } while (0)

#define GCOPY_B(K0, BUF)                                                          \
    do {                                                                          \
        const uint32_t Bb = uB[(BUF)];                                            \
        _Pragma("unroll")                                                         \
        for (int j = 0; j < 8; j++) {                                             \
            const int s = tid + j * 256;                                          \
            const int n = s >> 3, c = s & 7;                                      \
            cpasync16(Bb + n * (ASTRIDE * 2) + c * 16,                            \
                      (const char*)g_W1h + ((size_t)n * IND + SKIPD + (K0)) * 2 + c * 16); \
        }                                                                         \
    } while (0)

    GBUILD_A(0, 0);
    GCOPY_B(0, 0);
    cp_commit();
    cp_wait_all();
    __syncthreads();

    for (int it = 0; it < 8; it++) {
        const int buf = it & 1;
        if (it < 7) { GCOPY_B((it + 1) * 64, buf ^ 1); cp_commit(); }
#pragma unroll
        for (int ks = 0; ks < 4; ks++) {
            uint32_t af[2][4];
#pragma unroll
            for (int mt = 0; mt < 2; mt++)
                ldmx4(af[mt], uA[buf] +
                      ((warp_m * 32 + mt * 16 + a_row15) * ASTRIDE + ks * 16 + a_k8) * 2);
#pragma unroll
            for (int p = 0; p < 4; p++) {
                uint32_t bf[4];
                ldmx4(bf, uB[buf] +
                      ((warp_n * 64 + p * 16 + b_noff) * ASTRIDE + ks * 16 + b_k8) * 2);
                mma16816(acc[0][2 * p],     af[0], bf[0], bf[1]);
                mma16816(acc[0][2 * p + 1], af[0], bf[2], bf[3]);
                mma16816(acc[1][2 * p],     af[1], bf[0], bf[1]);
                mma16816(acc[1][2 * p + 1], af[1], bf[2], bf[3]);
            }
        }
        if (it < 7) GBUILD_A((it + 1) * 64, buf ^ 1);
        cp_wait_all();
        __syncthreads();
    }

    const int rA = warp_m * 32 + (lane >> 2);
    const int cA = warp_n * 64 + (lane & 3) * 2;
#pragma unroll
    for (int mt = 0; mt < 2; mt++)
#pragma unroll
        for (int hf = 0; hf < 2; hf++) {
            const int row = rA + mt * 16 + hf * 8;
            __half* dst = (__half*)g_Gh + (size_t)(g0 + row) * OUTD;
#pragma unroll
            for (int nt = 0; nt < 8; nt++) {
                const int col = cA + nt * 8;
                *(uint32_t*)(dst + col) = packh2(acc[mt][nt][2 * hf], acc[mt][nt][2 * hf + 1]);
            }
        }
}

__global__ __launch_bounds__(256, 2) void prep_kernel(const float* __restrict__ xyz_hi,
                                                      const float* __restrict__ xyz_lo,
                                                      const float* __restrict__ feat_lo) {
    extern __shared__ char sm[];
    if (blockIdx.x < 128) gemm_g_body(sm, feat_lo);
    else                  knn_body(sm, xyz_hi, xyz_lo);
}

// ---------------------------------------------------------------------------
// Fused kernel: 64x256 tile, 256 threads, 2 CTAs/SM, warp grid 2m x 4n.
// NEW in R9: epilogue-1 stages the IDW interp row-major (coalesced LDG.128)
// into the dead B-buffer SMEM, then combines via conflict-free LDS.
// ---------------------------------------------------------------------------
#define WSM_OFF  0
#define ISM_OFF  768
#define A_OFF    1536
#define A_BYTES  9216
#define H_OFF    1536
#define B_OFF    35328
#define B_BYTES  36864
#define SMEM_TOTAL 109056

__global__ __launch_bounds__(256, 2) void fused_kernel(
        const float* __restrict__ feat_skip,
        const float* __restrict__ b1,
        const float* __restrict__ b2,
        const float* __restrict__ gamma,
        const float* __restrict__ beta,
        float* __restrict__ out) {
    extern __shared__ char sm[];
    const uint32_t sb = smem_u32(sm);

    const int tid    = threadIdx.x;
    const int wid    = tid >> 5;
    const int lane   = tid & 31;
    const int warp_m = wid & 1;
    const int warp_n = wid >> 1;
    const int m0     = blockIdx.x * 64;
    const int bb     = m0 >> 13;

    float* Wsm = (float*)(sm + WSM_OFF);
    int*   Ism = (int*)(sm + ISM_OFF);
    for (int i = tid; i < 192; i += 256) {
        Wsm[i] = g_w[(size_t)m0 * 3 + i];
        Ism[i] = g_idx[(size_t)m0 * 3 + i];
    }

    const uint32_t uA[2] = { sb + A_OFF, sb + A_OFF + A_BYTES };
    const uint32_t uB[2] = { sb + B_OFF, sb + B_OFF + B_BYTES };
    const uint32_t uH    = sb + H_OFF;

    const int a_row15 = lane & 15;
    const int a_k8    = (lane & 16) ? 8 : 0;
    const int b_noff  = (lane & 7) + ((lane & 16) ? 8 : 0);
    const int b_k8    = (lane & 8) ? 8 : 0;
    const int fx = tid & 15, r0 = tid >> 4;

    float acc[2][8][4];
#pragma unroll
    for (int mt = 0; mt < 2; mt++)
#pragma unroll
        for (int nt = 0; nt < 8; nt++)
#pragma unroll
            for (int e = 0; e < 4; e++) acc[mt][nt][e] = 0.0f;

#define BUILD_A(K0, BUF)                                                          \
    do {                                                                          \
        char* Ab = sm + A_OFF + (BUF) * A_BYTES;                                  \
        _Pragma("unroll")                                                         \
        for (int i = 0; i < 4; i++) {                                             \
            const int row = r0 + i * 16;                                          \
            float4 v = *(const float4*)(feat_skip +                               \
                    (size_t)(m0 + row) * SKIPD + (K0) + fx * 4);                  \
            *(uint2*)(Ab + row * (ASTRIDE * 2) + fx * 8) =                        \
                make_uint2(packh2(v.x, v.y), packh2(v.z, v.w));                   \
        }                                                                         \
    } while (0)

#define COPY_B(WP, KDIM, K0, BUF)                                                 \
    do {                                                                          \
        const uint32_t Bb = uB[(BUF)];                                            \
        _Pragma("unroll")                                                         \
        for (int j = 0; j < 8; j++) {                                             \
            const int s = tid + j * 256;                                          \
            const int n = s >> 3, c = s & 7;                                      \
            cpasync16(Bb + n * (ASTRIDE * 2) + c * 16,                            \
                      (const char*)(WP) + ((size_t)n * (KDIM) + (K0)) * 2 + c * 16); \
        }                                                                         \
    } while (0)

#define MMA_CHUNK(ABASE, ASTR, AKOFF, BBUF)                                       \
    do {                                                                          \
        _Pragma("unroll")                                                         \
        for (int ks = 0; ks < 4; ks++) {                                          \
            uint32_t af[2][4];                                                    \
            _Pragma("unroll")                                                     \
            for (int mt = 0; mt < 2; mt++)                                        \
                ldmx4(af[mt], (ABASE) +                                           \
                      ((warp_m * 32 + mt * 16 + a_row15) * (ASTR) +               \
                       (AKOFF) + ks * 16 + a_k8) * 2);                            \
            _Pragma("unroll")                                                     \
            for (int p = 0; p < 4; p++) {                                         \
                uint32_t bf[4];                                                   \
                ldmx4(bf, (BBUF) +                                                \
                      ((warp_n * 64 + p * 16 + b_noff) * ASTRIDE +                \
                       ks * 16 + b_k8) * 2);                                      \
                mma16816(acc[0][2 * p],     af[0], bf[0], bf[1]);                 \
                mma16816(acc[0][2 * p + 1], af[0], bf[2], bf[3]);                 \
                mma16816(acc[1][2 * p],     af[1], bf[0], bf[1]);                 \
                mma16816(acc[1][2 * p + 1], af[1], bf[2], bf[3]);                 \
            }                                                                     \
        }                                                                         \
    } while (0)

    // ======================= GEMM 1: K = 256 (4 chunks) ==================
    BUILD_A(0, 0);
    COPY_B(g_W1h, IND, 0, 0);
    cp_commit();
    cp_wait_all();
    __syncthreads();

    for (int it = 0; it < 4; it++) {
        const int buf = it & 1;
        if (it < 3) { COPY_B(g_W1h, IND, (it + 1) * 64, buf ^ 1); cp_commit(); }
        MMA_CHUNK(uA[buf], ASTRIDE, 0, uB[buf]);
        if (it < 3) BUILD_A((it + 1) * 64, buf ^ 1);
        cp_wait_all();
        __syncthreads();
    }

    // ========= Epilogue 1a: stage interp rows (fp16) in B-buffer SMEM ====
    // Warp w handles rows 8w..8w+7; lane covers 8 halfs (16B) of each G row.
    {
        __half* interpS = (__half*)(sm + B_OFF);
#pragma unroll
        for (int rr = 0; rr < 8; rr++) {
            const int r = wid * 8 + rr;
            const float w0 = Wsm[r * 3 + 0];
            const float w1 = Wsm[r * 3 + 1];
            const float w2 = Wsm[r * 3 + 2];
            const __half* G0 = (const __half*)g_Gh + ((size_t)bb * Sv + Ism[r * 3 + 0]) * OUTD + lane * 8;
            const __half* G1 = (const __half*)g_Gh + ((size_t)bb * Sv + Ism[r * 3 + 1]) * OUTD + lane * 8;
            const __half* G2 = (const __half*)g_Gh + ((size_t)bb * Sv + Ism[r * 3 + 2]) * OUTD + lane * 8;
            uint4 u0 = *(const uint4*)G0;
            uint4 u1 = *(const uint4*)G1;
            uint4 u2 = *(const uint4*)G2;
            const uint32_t* p0 = (const uint32_t*)&u0;
            const uint32_t* p1 = (const uint32_t*)&u1;
            const uint32_t* p2 = (const uint32_t*)&u2;
            uint32_t o[4];
#pragma unroll
            for (int e = 0; e < 4; e++) {
                float2 f0 = __half22float2(*(const __half2*)&p0[e]);
                float2 f1 = __half22float2(*(const __half2*)&p1[e]);
                float2 f2 = __half22float2(*(const __half2*)&p2[e]);
                float vx = fmaf(w2, f2.x, fmaf(w1, f1.x, w0 * f0.x));
                float vy = fmaf(w2, f2.y, fmaf(w1, f1.y, w0 * f0.y));
                o[e] = packh2(vx, vy);
            }
            *(uint4*)(interpS + r * HSTRIDE + lane * 8) = *(uint4*)o;
        }
    }
    __syncthreads();

    // ========= Epilogue 1b: acc + b1 + interp; relu; -> H fp16 ===========
    {
        const __half* interpS = (const __half*)(sm + B_OFF);
        const int rA = warp_m * 32 + (lane >> 2);
        const int cA = warp_n * 64 + (lane & 3) * 2;
#pragma unroll
        for (int mt = 0; mt < 2; mt++)
#pragma unroll
            for (int hf = 0; hf < 2; hf++) {
                const int row = rA + mt * 16 + hf * 8;
#pragma unroll
                for (int nt = 0; nt < 8; nt++) {
                    const int col = cA + nt * 8;
                    float2 fi = __half22float2(*(const __half2*)(interpS + row * HSTRIDE + col));
                    float v0 = acc[mt][nt][2 * hf]     + b1[col]     + fi.x;
                    float v1 = acc[mt][nt][2 * hf + 1] + b1[col + 1] + fi.y;
                    v0 = fmaxf(v0, 0.0f);
                    v1 = fmaxf(v1, 0.0f);
                    *(uint32_t*)(sm + H_OFF + (row * HSTRIDE + col) * 2) = packh2(v0, v1);
                }
            }
    }
    __syncthreads();

    // ======================= GEMM 2: K = 256 (4 chunks) ==================
#pragma unroll
    for (int mt = 0; mt < 2; mt++)
#pragma unroll
        for (int nt = 0; nt < 8; nt++)
#pragma unroll
            for (int e = 0; e < 4; e++) acc[mt][nt][e] = 0.0f;

    COPY_B(g_W2h, OUTD, 0, 0);
    cp_commit();
    cp_wait_all();
    __syncthreads();

    for (int it = 0; it < 4; it++) {
        const int buf = it & 1;
        if (it < 3) { COPY_B(g_W2h, OUTD, (it + 1) * 64, buf ^ 1); cp_commit(); }
        MMA_CHUNK(uH, HSTRIDE, it * 64, uB[buf]);
        cp_wait_all();
        __syncthreads();
    }

    // ======================= Epilogue 2: LayerNorm -> out ================
    {
        float* Red  = (float*)(sm + B_OFF);   // [64][4]
        float* Red2 = Red + 256;              // [64][4]
        float* Mu   = Red2 + 256;             // [64]
        float* Rs   = Mu + 64;                // [64]

        const int rA = warp_m * 32 + (lane >> 2);
        const int cA = warp_n * 64 + (lane & 3) * 2;

#pragma unroll
        for (int mt = 0; mt < 2; mt++)
#pragma unroll
            for (int hf = 0; hf < 2; hf++) {
                const int row = rA + mt * 16 + hf * 8;
                float s = 0.0f, sq = 0.0f;
#pragma unroll
                for (int nt = 0; nt < 8; nt++) {
                    const int col = cA + nt * 8;
                    float v0 = acc[mt][nt][2 * hf]     + b2[col];
                    float v1 = acc[mt][nt][2 * hf + 1] + b2[col + 1];
                    s += v0 + v1;
                    sq = fmaf(v0, v0, fmaf(v1, v1, sq));
                }
                s  += __shfl_xor_sync(0xffffffffu, s, 1);
                s  += __shfl_xor_sync(0xffffffffu, s, 2);
                sq += __shfl_xor_sync(0xffffffffu, sq, 1);
                sq += __shfl_xor_sync(0xffffffffu, sq, 2);
                if ((lane & 3) == 0) {
                    Red[row * 4 + warp_n]  = s;
                    Red2[row * 4 + warp_n] = sq;
                }
            }
        __syncthreads();
        if (tid < 64) {
            float s  = Red[tid * 4]  + Red[tid * 4 + 1]  + Red[tid * 4 + 2]  + Red[tid * 4 + 3];
            float sq = Red2[tid * 4] + Red2[tid * 4 + 1] + Red2[tid * 4 + 2] + Red2[tid * 4 + 3];
            const float mu  = s * (1.0f / 256.0f);
            const float var = fmaxf(sq * (1.0f / 256.0f) - mu * mu, 0.0f);
            Mu[tid] = mu;
            Rs[tid] = rsqrtf(var + 1e-5f);
        }
        __syncthreads();

#pragma unroll
        for (int mt = 0; mt < 2; mt++)
#pragma unroll
            for (int hf = 0; hf < 2; hf++) {
                const int row  = rA + mt * 16 + hf * 8;
                const float mu = Mu[row], rstd = Rs[row];
                float* dst = out + (size_t)(m0 + row) * OUTD;
#pragma unroll
                for (int nt = 0; nt < 8; nt++) {
                    const int col = cA + nt * 8;
                    float v0 = acc[mt][nt][2 * hf]     + b2[col];
                    float v1 = acc[mt][nt][2 * hf + 1] + b2[col + 1];
                    float2 o;
                    o.x = fmaf((v0 - mu) * rstd, gamma[col],     beta[col]);
                    o.y = fmaf((v1 - mu) * rstd, gamma[col + 1], beta[col + 1]);
                    *(float2*)(dst + col) = o;
                }
            }
    }
}

// ---------------------------------------------------------------------------
extern "C" void kernel_launch(void* const* d_in, const int* in_sizes, int n_in,
                              void* d_out, int out_size) {
    const float* xyz_hi    = (const float*)d_in[0];
    const float* xyz_lo    = (const float*)d_in[1];
    const float* feat_skip = (const float*)d_in[2];
    const float* feat_lo   = (const float*)d_in[3];
    const float* W1        = (const float*)d_in[4];
    const float* b1        = (const float*)d_in[5];
    const float* W2        = (const float*)d_in[6];
    const float* b2        = (const float*)d_in[7];
    const float* gamma     = (const float*)d_in[8];
    const float* beta      = (const float*)d_in[9];
    float* out = (float*)d_out;

    __half* w1h; cudaGetSymbolAddress((void**)&w1h, g_W1h);
    __half* w2h; cudaGetSymbolAddress((void**)&w2h, g_W2h);

    transpose_both<<<dim3(8, 32), dim3(32, 8)>>>(W1, W2, w1h, w2h);

    cudaFuncSetAttribute(prep_kernel,
                         cudaFuncAttributeMaxDynamicSharedMemorySize, GSMEM);
    prep_kernel<<<256, 256, GSMEM>>>(xyz_hi, xyz_lo, feat_lo);

    cudaFuncSetAttribute(fused_kernel,
                         cudaFuncAttributeMaxDynamicSharedMemorySize, SMEM_TOTAL);
    fused_kernel<<<(Bv * Nv) / 64, 256, SMEM_TOTAL>>>(
        feat_skip, b1, b2, gamma, beta, out);
}

// round 10
// speedup vs baseline: 1.1597x; 1.1597x over previous
#include <cuda_runtime.h>
#include <cuda_fp16.h>
#include <math.h>
#include <stdint.h>

// Problem constants
#define Bv     4
#define Nv     8192
#define Sv     2048
#define LOWD   512
#define SKIPD  256
#define OUTD   256
#define IND    768

// Scratch (device globals; no allocation allowed)
__device__ float  g_w[(size_t)Bv * Nv * 3];
__device__ int    g_idx[(size_t)Bv * Nv * 3];
__device__ __half g_W1h[(size_t)OUTD * IND];     // W1^T fp16 [n][k]
__device__ __half g_W2h[(size_t)OUTD * OUTD];    // W2^T fp16 [n][k]
__device__ __half g_Gh[(size_t)Bv * Sv * OUTD];  // feat_lo @ W1[256:] (fp16, 4 MB)
__device__ int    g_flag;                        // W1h-bottom ready counter

// ---------------------------------------------------------------------------
// Helpers
// ---------------------------------------------------------------------------
__device__ __forceinline__ uint32_t smem_u32(const void* p) {
    uint32_t a;
    asm("{ .reg .u64 t; cvta.to.shared.u64 t, %1; cvt.u32.u64 %0, t; }"
        : "=r"(a) : "l"(p));
    return a;
}
__device__ __forceinline__ void ldmx4(uint32_t (&r)[4], uint32_t addr) {
    asm volatile("ldmatrix.sync.aligned.m8n8.x4.shared.b16 {%0,%1,%2,%3}, [%4];"
                 : "=r"(r[0]), "=r"(r[1]), "=r"(r[2]), "=r"(r[3]) : "r"(addr));
}
__device__ __forceinline__ void mma16816(float (&d)[4], const uint32_t (&a)[4],
                                         uint32_t b0, uint32_t b1) {
    asm volatile("mma.sync.aligned.m16n8k16.row.col.f32.f16.f16.f32 "
                 "{%0,%1,%2,%3}, {%4,%5,%6,%7}, {%8,%9}, {%0,%1,%2,%3};"
                 : "+f"(d[0]), "+f"(d[1]), "+f"(d[2]), "+f"(d[3])
                 : "r"(a[0]), "r"(a[1]), "r"(a[2]), "r"(a[3]), "r"(b0), "r"(b1));
}
__device__ __forceinline__ void cpasync16(uint32_t s, const void* g) {
    asm volatile("cp.async.cg.shared.global [%0], [%1], 16;" :: "r"(s), "l"(g));
}
__device__ __forceinline__ void cp_commit() {
    asm volatile("cp.async.commit_group;" ::: "memory");
}
__device__ __forceinline__ void cp_wait_all() {
    asm volatile("cp.async.wait_group 0;" ::: "memory");
}
__device__ __forceinline__ uint32_t packh2(float a, float b) {
    __half2 h = __floats2half2_rn(a, b);
    return *(uint32_t*)&h;
}

#define ASTRIDE  72      // halfs
#define HSTRIDE  264     // halfs

// ---------------------------------------------------------------------------
// PREP kernel (288 blocks => ONE wave at 2 CTAs/SM, all co-resident):
//   [0, 32)    transpose: W1-bottom first -> g_flag; then W1-top + W2
//   [32, 160)  gemm_g   : G = feat_lo @ W1[256:]^T -> g_Gh (spins on g_flag)
//   [160, 288) knn      : full-scan 3-NN + IDW
// ---------------------------------------------------------------------------
#define GA_BYTES 9216     // 64 * 72 * 2
#define GB_BYTES 36864    // 256 * 72 * 2
#define GSMEM    (2 * GA_BYTES + 2 * GB_BYTES)   // 92160

// one 32x32 transpose tile: src fp32 [k][OUTD] -> dst fp16 [n][Kdim]
__device__ __forceinline__ void do_tile(float* t, const float* __restrict__ src,
                                        __half* dst, int Kdim, int k0, int n0,
                                        int tx, int ty) {
    __syncthreads();
#pragma unroll
    for (int j = 0; j < 32; j += 8)
        t[(ty + j) * 33 + tx] = src[(size_t)(k0 + ty + j) * OUTD + n0 + tx];
    __syncthreads();
#pragma unroll
    for (int j = 0; j < 32; j += 8)
        dst[(size_t)(n0 + ty + j) * Kdim + k0 + tx] = __float2half_rn(t[tx * 33 + ty + j]);
}

__device__ __forceinline__ void transpose_body(char* sm,
                                               const float* __restrict__ W1,
                                               const float* __restrict__ W2) {
    float* t = (float*)sm;
    const int tb  = blockIdx.x;                   // 0..31
    const int tid = threadIdx.x;
    const int tx  = tid & 31, ty = (tid >> 5) & 7;

    // Phase 1: W1 bottom (k in [256,768)) -> g_W1h ; 128 tiles, 4 per block
    if (tid < 256) {
#pragma unroll
        for (int i = 0; i < 4; i++) {
            const int tile = tb * 4 + i;                  // 0..127
            const int k0 = SKIPD + (tile >> 3) * 32;
            const int n0 = (tile & 7) * 32;
            do_tile(t, W1, g_W1h, IND, k0, n0, tx, ty);
        }
    }
    __threadfence();
    __syncthreads();
    if (tid == 0) atomicAdd(&g_flag, 1);

    // Phase 2: W1 top + W2 (only needed by the NEXT kernel)
    if (tid < 256) {
#pragma unroll
        for (int i = 0; i < 4; i++) {
            const int tile = tb * 4 + i;                  // 0..127
            if (tile < 64) {
                do_tile(t, W1, g_W1h, IND, (tile >> 3) * 32, (tile & 7) * 32, tx, ty);
            } else {
                const int t2 = tile - 64;
                do_tile(t, W2, g_W2h, OUTD, (t2 >> 3) * 32, (t2 & 7) * 32, tx, ty);
            }
        }
    }
}

__device__ __forceinline__ void knn_body(char* sm,
                                         const float* __restrict__ xyz_hi,
                                         const float* __restrict__ xyz_lo) {
    float4* P = (float4*)sm;   // 32 KB
    const int bid   = blockIdx.x - 160;
    const int b     = bid >> 5;
    const int qbase = (bid & 31) * 256;
    const int tid   = threadIdx.x;

    for (int s = tid; s < Sv; s += 256) {
        float x = xyz_lo[((size_t)b * Sv + s) * 3 + 0];
        float y = xyz_lo[((size_t)b * Sv + s) * 3 + 1];
        float z = xyz_lo[((size_t)b * Sv + s) * 3 + 2];
        P[s] = make_float4(-2.0f * x, -2.0f * y, -2.0f * z,
                           fmaf(z, z, fmaf(y, y, x * x)));
    }
    __syncthreads();

    const int q = b * Nv + qbase + tid;
    const float qx = xyz_hi[(size_t)q * 3 + 0];
    const float qy = xyz_hi[(size_t)q * 3 + 1];
    const float qz = xyz_hi[(size_t)q * 3 + 2];
    const float qq = fmaf(qz, qz, fmaf(qy, qy, qx * qx));

    float d0 = 1e30f, d1 = 1e30f, d2 = 1e30f;
    int   i0 = 0,     i1 = 0,     i2 = 0;

#define INS3(E, S)                                                       \
    {                                                                    \
        bool l2 = (E) < d2, l1 = (E) < d1, l0 = (E) < d0;                \
        d2 = l1 ? d1 : (l2 ? (E) : d2);  i2 = l1 ? i1 : (l2 ? (S) : i2); \
        d1 = l0 ? d0 : (l1 ? (E) : d1);  i1 = l0 ? i0 : (l1 ? (S) : i1); \
        d0 = l0 ? (E) : d0;              i0 = l0 ? (S) : i0;             \
    }
    for (int s = 0; s < Sv; s += 4) {
        float4 p0 = P[s + 0], p1 = P[s + 1], p2 = P[s + 2], p3 = P[s + 3];
        float e0 = fmaf(qx, p0.x, fmaf(qy, p0.y, fmaf(qz, p0.z, p0.w)));
        float e1 = fmaf(qx, p1.x, fmaf(qy, p1.y, fmaf(qz, p1.z, p1.w)));
        float e2 = fmaf(qx, p2.x, fmaf(qy, p2.y, fmaf(qz, p2.z, p2.w)));
        float e3 = fmaf(qx, p3.x, fmaf(qy, p3.y, fmaf(qz, p3.z, p3.w)));
        float m = fminf(fminf(e0, e1), fminf(e2, e3));
        if (m < d2) {
            INS3(e0, s + 0); INS3(e1, s + 1); INS3(e2, s + 2); INS3(e3, s + 3);
        }
    }
#undef INS3

    float r0 = 1.0f / (sqrtf(fmaxf(d0 + qq, 0.0f)) + 1e-8f);
    float r1 = 1.0f / (sqrtf(fmaxf(d1 + qq, 0.0f)) + 1e-8f);
    float r2 = 1.0f / (sqrtf(fmaxf(d2 + qq, 0.0f)) + 1e-8f);
    float inv = 1.0f / (r0 + r1 + r2);
    g_w[(size_t)q * 3 + 0] = r0 * inv;
    g_w[(size_t)q * 3 + 1] = r1 * inv;
    g_w[(size_t)q * 3 + 2] = r2 * inv;
    g_idx[(size_t)q * 3 + 0] = i0;
    g_idx[(size_t)q * 3 + 1] = i1;
    g_idx[(size_t)q * 3 + 2] = i2;
}

__device__ __forceinline__ void gemm_g_body(char* sm, const float* __restrict__ feat_lo) {
    const uint32_t sb = smem_u32(sm);
    const int tid    = threadIdx.x;
    const int wid    = tid >> 5;
    const int lane   = tid & 31;
    const int warp_m = wid & 1;
    const int warp_n = wid >> 1;
    const int g0     = (blockIdx.x - 32) * 64;

    const uint32_t uA[2] = { sb, sb + GA_BYTES };
    const uint32_t uB[2] = { sb + 2 * GA_BYTES, sb + 2 * GA_BYTES + GB_BYTES };

    const int a_row15 = lane & 15;
    const int a_k8    = (lane & 16) ? 8 : 0;
    const int b_noff  = (lane & 7) + ((lane & 16) ? 8 : 0);
    const int b_k8    = (lane & 8) ? 8 : 0;
    const int fx = tid & 15, r0 = tid >> 4;

    float acc[2][8][4];
#pragma unroll
    for (int mt = 0; mt < 2; mt++)
#pragma unroll
        for (int nt = 0; nt < 8; nt++)
#pragma unroll
            for (int e = 0; e < 4; e++) acc[mt][nt][e] = 0.0f;

#define GBUILD_A(K0, BUF)                                                         \
    do {                                                                          \
        char* Ab = sm + (BUF) * GA_BYTES;                                         \
        _Pragma("unroll")                                                         \
        for (int i = 0; i < 4; i++) {                                             \
            const int row = r0 + i * 16;                                          \
            float4 v = *(const float4*)(feat_lo + (size_t)(g0 + row) * LOWD + (K0) + fx * 4); \
            *(uint2*)(Ab + row * (ASTRIDE * 2) + fx * 8) =                        \
                make_uint2(packh2(v.x, v.y), packh2(v.z, v.w));                   \
        }                                                                         \
    } while (0)

#define GCOPY_B(K0, BUF)                                                          \
    do {                                                                          \
        const uint32_t Bb = uB[(BUF)];                                            \
        _Pragma("unroll")                                                         \
        for (int j = 0; j < 8; j++) {                                             \
            const int s = tid + j * 256;                                          \
            const int n = s >> 3, c = s & 7;                                      \
            cpasync16(Bb + n * (ASTRIDE * 2) + c * 16,                            \
                      (const char*)g_W1h + ((size_t)n * IND + SKIPD + (K0)) * 2 + c * 16); \
        }                                                                         \
    } while (0)

    GBUILD_A(0, 0);

    // wait for W1h-bottom (written by co-resident transpose blocks)
    if (tid == 0) {
        while (*(volatile int*)&g_flag < 32) { }
    }
    __syncthreads();
    __threadfence();

    GCOPY_B(0, 0);
    cp_commit();
    cp_wait_all();
    __syncthreads();

    for (int it = 0; it < 8; it++) {
        const int buf = it & 1;
        if (it < 7) { GCOPY_B((it + 1) * 64, buf ^ 1); cp_commit(); }
#pragma unroll
        for (int ks = 0; ks < 4; ks++) {
            uint32_t af[2][4];
#pragma unroll
            for (int mt = 0; mt < 2; mt++)
                ldmx4(af[mt], uA[buf] +
                      ((warp_m * 32 + mt * 16 + a_row15) * ASTRIDE + ks * 16 + a_k8) * 2);
#pragma unroll
            for (int p = 0; p < 4; p++) {
                uint32_t bf[4];
                ldmx4(bf, uB[buf] +
                      ((warp_n * 64 + p * 16 + b_noff) * ASTRIDE + ks * 16 + b_k8) * 2);
                mma16816(acc[0][2 * p],     af[0], bf[0], bf[1]);
                mma16816(acc[0][2 * p + 1], af[0], bf[2], bf[3]);
                mma16816(acc[1][2 * p],     af[1], bf[0], bf[1]);
                mma16816(acc[1][2 * p + 1], af[1], bf[2], bf[3]);
            }
        }
        if (it < 7) GBUILD_A((it + 1) * 64, buf ^ 1);
        cp_wait_all();
        __syncthreads();
    }

    const int rA = warp_m * 32 + (lane >> 2);
    const int cA = warp_n * 64 + (lane & 3) * 2;
#pragma unroll
    for (int mt = 0; mt < 2; mt++)
#pragma unroll
        for (int hf = 0; hf < 2; hf++) {
            const int row = rA + mt * 16 + hf * 8;
            __half* dst = (__half*)g_Gh + (size_t)(g0 + row) * OUTD;
#pragma unroll
            for (int nt = 0; nt < 8; nt++) {
                const int col = cA + nt * 8;
                *(uint32_t*)(dst + col) = packh2(acc[mt][nt][2 * hf], acc[mt][nt][2 * hf + 1]);
            }
        }
}

__global__ __launch_bounds__(256, 2) void prep_kernel(const float* __restrict__ xyz_hi,
                                                      const float* __restrict__ xyz_lo,
                                                      const float* __restrict__ feat_lo,
                                                      const float* __restrict__ W1,
                                                      const float* __restrict__ W2) {
    extern __shared__ char sm[];
    if (blockIdx.x < 32)       transpose_body(sm, W1, W2);
    else if (blockIdx.x < 160) gemm_g_body(sm, feat_lo);
    else                       knn_body(sm, xyz_hi, xyz_lo);
}

// ---------------------------------------------------------------------------
// Fused kernel: 64x256 tile, 256 threads, 2 CTAs/SM (R6-proven structure).
// ---------------------------------------------------------------------------
#define WSM_OFF  0
#define ISM_OFF  768
#define A_OFF    1536
#define A_BYTES  9216
#define H_OFF    1536
#define B_OFF    35328
#define B_BYTES  36864
#define SMEM_TOTAL 109056

__global__ __launch_bounds__(256, 2) void fused_kernel(
        const float* __restrict__ feat_skip,
        const float* __restrict__ b1,
        const float* __restrict__ b2,
        const float* __restrict__ gamma,
        const float* __restrict__ beta,
        float* __restrict__ out) {
    extern __shared__ char sm[];
    const uint32_t sb = smem_u32(sm);

    const int tid    = threadIdx.x;
    const int wid    = tid >> 5;
    const int lane   = tid & 31;
    const int warp_m = wid & 1;
    const int warp_n = wid >> 1;
    const int m0     = blockIdx.x * 64;
    const int bb     = m0 >> 13;

    float* Wsm = (float*)(sm + WSM_OFF);
    int*   Ism = (int*)(sm + ISM_OFF);
    for (int i = tid; i < 192; i += 256) {
        Wsm[i] = g_w[(size_t)m0 * 3 + i];
        Ism[i] = g_idx[(size_t)m0 * 3 + i];
    }

    const uint32_t uA[2] = { sb + A_OFF, sb + A_OFF + A_BYTES };
    const uint32_t uB[2] = { sb + B_OFF, sb + B_OFF + B_BYTES };
    const uint32_t uH    = sb + H_OFF;

    const int a_row15 = lane & 15;
    const int a_k8    = (lane & 16) ? 8 : 0;
    const int b_noff  = (lane & 7) + ((lane & 16) ? 8 : 0);
    const int b_k8    = (lane & 8) ? 8 : 0;
    const int fx = tid & 15, r0 = tid >> 4;

    float acc[2][8][4];
#pragma unroll
    for (int mt = 0; mt < 2; mt++)
#pragma unroll
        for (int nt = 0; nt < 8; nt++)
#pragma unroll
            for (int e = 0; e < 4; e++) acc[mt][nt][e] = 0.0f;

#define BUILD_A(K0, BUF)                                                          \
    do {                                                                          \
        char* Ab = sm + A_OFF + (BUF) * A_BYTES;                                  \
        _Pragma("unroll")                                                         \
        for (int i = 0; i < 4; i++) {                                             \
            const int row = r0 + i * 16;                                          \
            float4 v = *(const float4*)(feat_skip +                               \
                    (size_t)(m0 + row) * SKIPD + (K0) + fx * 4);                  \
            *(uint2*)(Ab + row * (ASTRIDE * 2) + fx * 8) =                        \
                make_uint2(packh2(v.x, v.y), packh2(v.z, v.w));                   \
        }                                                                         \
    } while (0)

#define COPY_B(WP, KDIM, K0, BUF)                                                 \
    do {                                                                          \
        const uint32_t Bb = uB[(BUF)];                                            \
        _Pragma("unroll")                                                         \
        for (int j = 0; j < 8; j++) {                                             \
            const int s = tid + j * 256;                                          \
            const int n = s >> 3, c = s & 7;                                      \
            cpasync16(Bb + n * (ASTRIDE * 2) + c * 16,                            \
                      (const char*)(WP) + ((size_t)n * (KDIM) + (K0)) * 2 + c * 16); \
        }                                                                         \
    } while (0)

#define MMA_CHUNK(ABASE, ASTR, AKOFF, BBUF)                                       \
    do {                                                                          \
        _Pragma("unroll")                                                         \
        for (int ks = 0; ks < 4; ks++) {                                          \
            uint32_t af[2][4];                                                    \
            _Pragma("unroll")                                                     \
            for (int mt = 0; mt < 2; mt++)                                        \
                ldmx4(af[mt], (ABASE) +                                           \
                      ((warp_m * 32 + mt * 16 + a_row15) * (ASTR) +               \
                       (AKOFF) + ks * 16 + a_k8) * 2);                            \
            _Pragma("unroll")                                                     \
            for (int p = 0; p < 4; p++) {                                         \
                uint32_t bf[4];                                                   \
                ldmx4(bf, (BBUF) +                                                \
                      ((warp_n * 64 + p * 16 + b_noff) * ASTRIDE +                \
                       ks * 16 + b_k8) * 2);                                      \
                mma16816(acc[0][2 * p],     af[0], bf[0], bf[1]);                 \
                mma16816(acc[0][2 * p + 1], af[0], bf[2], bf[3]);                 \
                mma16816(acc[1][2 * p],     af[1], bf[0], bf[1]);                 \
                mma16816(acc[1][2 * p + 1], af[1], bf[2], bf[3]);                 \
            }                                                                     \
        }                                                                         \
    } while (0)

    // ======================= GEMM 1: K = 256 (4 chunks) ==================
    BUILD_A(0, 0);
    COPY_B(g_W1h, IND, 0, 0);
    cp_commit();
    cp_wait_all();
    __syncthreads();

    for (int it = 0; it < 4; it++) {
        const int buf = it & 1;
        if (it < 3) { COPY_B(g_W1h, IND, (it + 1) * 64, buf ^ 1); cp_commit(); }
        MMA_CHUNK(uA[buf], ASTRIDE, 0, uB[buf]);
        if (it < 3) BUILD_A((it + 1) * 64, buf ^ 1);
        cp_wait_all();
        __syncthreads();
    }

    // ========= Epilogue 1: acc += b1 + IDW(Gh); relu; -> H fp16 ==========
    {
        const int rA = warp_m * 32 + (lane >> 2);
        const int cA = warp_n * 64 + (lane & 3) * 2;
#pragma unroll
        for (int mt = 0; mt < 2; mt++)
#pragma unroll
            for (int hf = 0; hf < 2; hf++) {
                const int row = rA + mt * 16 + hf * 8;
                const float w0 = Wsm[row * 3 + 0];
                const float w1 = Wsm[row * 3 + 1];
                const float w2 = Wsm[row * 3 + 2];
                const __half* G0 = (const __half*)g_Gh + ((size_t)bb * Sv + Ism[row * 3 + 0]) * OUTD;
                const __half* G1 = (const __half*)g_Gh + ((size_t)bb * Sv + Ism[row * 3 + 1]) * OUTD;
                const __half* G2 = (const __half*)g_Gh + ((size_t)bb * Sv + Ism[row * 3 + 2]) * OUTD;
#pragma unroll
                for (int nt = 0; nt < 8; nt++) {
                    const int col = cA + nt * 8;
                    float2 f0 = __half22float2(*(const __half2*)(G0 + col));
                    float2 f1 = __half22float2(*(const __half2*)(G1 + col));
                    float2 f2 = __half22float2(*(const __half2*)(G2 + col));
                    float v0 = acc[mt][nt][2 * hf]     + b1[col];
                    float v1 = acc[mt][nt][2 * hf + 1] + b1[col + 1];
                    v0 = fmaf(w0, f0.x, fmaf(w1, f1.x, fmaf(w2, f2.x, v0)));
                    v1 = fmaf(w0, f0.y, fmaf(w1, f1.y, fmaf(w2, f2.y, v1)));
                    v0 = fmaxf(v0, 0.0f);
                    v1 = fmaxf(v1, 0.0f);
                    *(uint32_t*)(sm + H_OFF + (row * HSTRIDE + col) * 2) = packh2(v0, v1);
                }
            }
    }
    __syncthreads();

    // ======================= GEMM 2: K = 256 (4 chunks) ==================
#pragma unroll
    for (int mt = 0; mt < 2; mt++)
#pragma unroll
        for (int nt = 0; nt < 8; nt++)
#pragma unroll
            for (int e = 0; e < 4; e++) acc[mt][nt][e] = 0.0f;

    COPY_B(g_W2h, OUTD, 0, 0);
    cp_commit();
    cp_wait_all();
    __syncthreads();

    for (int it = 0; it < 4; it++) {
        const int buf = it & 1;
        if (it < 3) { COPY_B(g_W2h, OUTD, (it + 1) * 64, buf ^ 1); cp_commit(); }
        MMA_CHUNK(uH, HSTRIDE, it * 64, uB[buf]);
        cp_wait_all();
        __syncthreads();
    }

    // ======================= Epilogue 2: LayerNorm -> out ================
    {
        float* Red  = (float*)(sm + B_OFF);   // [64][4]
        float* Red2 = Red + 256;              // [64][4]
        float* Mu   = Red2 + 256;             // [64]
        float* Rs   = Mu + 64;                // [64]

        const int rA = warp_m * 32 + (lane >> 2);
        const int cA = warp_n * 64 + (lane & 3) * 2;

#pragma unroll
        for (int mt = 0; mt < 2; mt++)
#pragma unroll
            for (int hf = 0; hf < 2; hf++) {
                const int row = rA + mt * 16 + hf * 8;
                float s = 0.0f, sq = 0.0f;
#pragma unroll
                for (int nt = 0; nt < 8; nt++) {
                    const int col = cA + nt * 8;
                    float v0 = acc[mt][nt][2 * hf]     + b2[col];
                    float v1 = acc[mt][nt][2 * hf + 1] + b2[col + 1];
                    acc[mt][nt][2 * hf]     = v0;   // fold b2 in place for pass 2
                    acc[mt][nt][2 * hf + 1] = v1;
                    s += v0 + v1;
                    sq = fmaf(v0, v0, fmaf(v1, v1, sq));
                }
                s  += __shfl_xor_sync(0xffffffffu, s, 1);
                s  += __shfl_xor_sync(0xffffffffu, s, 2);
                sq += __shfl_xor_sync(0xffffffffu, sq, 1);
                sq += __shfl_xor_sync(0xffffffffu, sq, 2);
                if ((lane & 3) == 0) {
                    Red[row * 4 + warp_n]  = s;
                    Red2[row * 4 + warp_n] = sq;
                }
            }
        __syncthreads();
        if (tid < 64) {
            float s  = Red[tid * 4]  + Red[tid * 4 + 1]  + Red[tid * 4 + 2]  + Red[tid * 4 + 3];
            float sq = Red2[tid * 4] + Red2[tid * 4 + 1] + Red2[tid * 4 + 2] + Red2[tid * 4 + 3];
            const float mu  = s * (1.0f / 256.0f);
            const float var = fmaxf(sq * (1.0f / 256.0f) - mu * mu, 0.0f);
            Mu[tid] = mu;
            Rs[tid] = rsqrtf(var + 1e-5f);
        }
        __syncthreads();

#pragma unroll
        for (int mt = 0; mt < 2; mt++)
#pragma unroll
            for (int hf = 0; hf < 2; hf++) {
                const int row  = rA + mt * 16 + hf * 8;
                const float mu = Mu[row], rstd = Rs[row];
                float* dst = out + (size_t)(m0 + row) * OUTD;
#pragma unroll
                for (int nt = 0; nt < 8; nt++) {
                    const int col = cA + nt * 8;
                    float2 o;
                    o.x = fmaf((acc[mt][nt][2 * hf]     - mu) * rstd, gamma[col],     beta[col]);
                    o.y = fmaf((acc[mt][nt][2 * hf + 1] - mu) * rstd, gamma[col + 1], beta[col + 1]);
                    *(float2*)(dst + col) = o;
                }
            }
    }
}

// ---------------------------------------------------------------------------
extern "C" void kernel_launch(void* const* d_in, const int* in_sizes, int n_in,
                              void* d_out, int out_size) {
    const float* xyz_hi    = (const float*)d_in[0];
    const float* xyz_lo    = (const float*)d_in[1];
    const float* feat_skip = (const float*)d_in[2];
    const float* feat_lo   = (const float*)d_in[3];
    const float* W1        = (const float*)d_in[4];
    const float* b1        = (const float*)d_in[5];
    const float* W2        = (const float*)d_in[6];
    const float* b2        = (const float*)d_in[7];
    const float* gamma     = (const float*)d_in[8];
    const float* beta      = (const float*)d_in[9];
    float* out = (float*)d_out;

    int* flag_ptr;
    cudaGetSymbolAddress((void**)&flag_ptr, g_flag);
    cudaMemsetAsync(flag_ptr, 0, sizeof(int));

    cudaFuncSetAttribute(prep_kernel,
                         cudaFuncAttributeMaxDynamicSharedMemorySize, GSMEM);
    prep_kernel<<<288, 256, GSMEM>>>(xyz_hi, xyz_lo, feat_lo, W1, W2);

    cudaFuncSetAttribute(fused_kernel,
                         cudaFuncAttributeMaxDynamicSharedMemorySize, SMEM_TOTAL);
    fused_kernel<<<(Bv * Nv) / 64, 256, SMEM_TOTAL>>>(
        feat_skip, b1, b2, gamma, beta, out);
}